// round 14
// baseline (speedup 1.0000x reference)
#include <cuda_runtime.h>
#include <cuda_bf16.h>
#include <cstdint>
#include <cmath>

// ============================================================================
// ProtoNetLayer — fused single-pass mma.sync bf16 kernel (sm_103-family safe).
//
//   scores[n,c] = -sqrt(max(1 + |P_c|^2 - 2 * z_n . P_c, 0))
//   phase 1: Y = X @ projT^T - c   (K=1024, cp.async/ldmatrix/mma pipeline)
//   norm:    z = Y / max(|Y|,eps)  -> bf16 in shared memory
//   phase 2: S = z @ P^T (K=256, A from smem Z panels) + sqrt epilogue
//
// R13 == R12 resubmitted (previous run died to a container-infra failure, not
// a kernel error):
//      (a) prep at 80 finer blocks (latency-bound; more SM coverage);
//      (b) 3-stage cp.async B pipeline (wait_group 1) in both phases — B gets
//          two mma-stages of latency slack instead of one; A on same 3-buffer
//          rotation; smem 208KB;
//      (c) g_c/g_p2 prefetched to registers at kernel start (no L2 stall at
//          the norm epilogue).
// ============================================================================

#define N_ROWS  32768
#define D_IN    1024
#define D_PROJ  256
#define N_CLS   256
#define TM      128
#define KT      64
#define NS1     16        // phase-1 k stages
#define NS2     4         // phase-2 k stages

// fused-kernel smem layout (bytes)
#define OFF_A    0        // A stages: 3 x 16384  (128 rows x 128B)
#define OFF_B    49152    // B stages: 3 x 32768  (256 rows x 128B)
#define OFF_Z    147456   // Z panels: 4 x 16384  (128 rows x 128B)
#define SMEMF    212992
// reuse of dead A-buf0 after phase-1 mainloop:
#define OFF_C    0        // c[256] f32
#define OFF_P2   1024     // p2[256] f32
#define OFF_RED  2048     // red[128][4] f32

// device-global scratch (no runtime allocation allowed)
__device__ __align__(256) __nv_bfloat16 g_Bw[D_PROJ * D_IN];   // projT bf16 [256][1024]
__device__ __align__(256) __nv_bfloat16 g_Bp[N_CLS * D_PROJ];  // prototypes bf16 [256][256]
__device__ float g_cpart[64 * D_PROJ];                         // partial c per transpose block
__device__ float g_c[D_PROJ];                                  // mean @ proj
__device__ float g_p2[N_CLS];                                  // |P_c|^2

// ---------------------------------------------------------------------------
// asm helpers (family-agnostic: sm_75/sm_80 features)
// ---------------------------------------------------------------------------
__device__ __forceinline__ uint32_t smem_u32(const void* p) {
    uint32_t a;
    asm("{ .reg .u64 t; cvta.to.shared.u64 t, %1; cvt.u32.u64 %0, t; }" : "=r"(a) : "l"(p));
    return a;
}
__device__ __forceinline__ void ldmx4(uint32_t* r, uint32_t a) {
    asm volatile("ldmatrix.sync.aligned.m8n8.x4.shared.b16 {%0,%1,%2,%3}, [%4];"
                 : "=r"(r[0]), "=r"(r[1]), "=r"(r[2]), "=r"(r[3]) : "r"(a));
}
__device__ __forceinline__ void mmabf16(float* c, const uint32_t* a, uint32_t b0, uint32_t b1) {
    asm volatile("mma.sync.aligned.m16n8k16.row.col.f32.bf16.bf16.f32 "
                 "{%0,%1,%2,%3}, {%4,%5,%6,%7}, {%8,%9}, {%0,%1,%2,%3};"
                 : "+f"(c[0]), "+f"(c[1]), "+f"(c[2]), "+f"(c[3])
                 : "r"(a[0]), "r"(a[1]), "r"(a[2]), "r"(a[3]), "r"(b0), "r"(b1));
}
__device__ __forceinline__ void cp16(uint32_t d, const void* s) {
    asm volatile("cp.async.cg.shared.global [%0], [%1], 16;" :: "r"(d), "l"(s) : "memory");
}
#define CP_COMMIT() asm volatile("cp.async.commit_group;" ::: "memory")
#define CP_WAIT0()  asm volatile("cp.async.wait_group 0;" ::: "memory")
#define CP_WAIT1()  asm volatile("cp.async.wait_group 1;" ::: "memory")

// 32(M) x 64(N) warp-tile mma over one K=64 stage (swizzled smem, 128B rows)
__device__ __forceinline__ void mma_stage(uint32_t Abase, uint32_t Bbase,
                                          int lane, int wm, int wn,
                                          float (&acc)[2][8][4]) {
    const int ra  = (lane & 7) + ((lane >> 3) & 1) * 8;
    const int kxa = ((lane >> 4) & 1) * 16;
    const int rb  = (lane & 7) + ((lane >> 4) & 1) * 8;
    const int kxb = ((lane >> 3) & 1) * 16;
    const int xa = (lane & 7) << 4;
    const uint32_t Aw = Abase + (uint32_t)(wm * 32 + ra) * 128;
    const uint32_t Bw = Bbase + (uint32_t)(wn * 64 + rb) * 128;
    #pragma unroll
    for (int k16 = 0; k16 < 4; k16++) {
        uint32_t aF[2][4], bF[4][4];
        #pragma unroll
        for (int mi = 0; mi < 2; mi++)
            ldmx4(aF[mi], Aw + mi * 16 * 128 + (uint32_t)((k16 * 32 + kxa) ^ xa));
        #pragma unroll
        for (int nj = 0; nj < 4; nj++)
            ldmx4(bF[nj], Bw + nj * 16 * 128 + (uint32_t)((k16 * 32 + kxb) ^ xa));
        #pragma unroll
        for (int mi = 0; mi < 2; mi++)
            #pragma unroll
            for (int nj = 0; nj < 4; nj++) {
                mmabf16(acc[mi][2 * nj],     aF[mi], bF[nj][0], bF[nj][1]);
                mmabf16(acc[mi][2 * nj + 1], aF[mi], bF[nj][2], bF[nj][3]);
            }
    }
}

// ---------------------------------------------------------------------------
// Prep (80 blocks x 256 threads):
//  blocks 0..63 : projT transpose tile (16 d-rows) + partial c for those rows
//  blocks 64..79: prototypes f32->bf16 convert (16 rows) + fused p2
// Then proto_prep2<<<1,256>>> folds the 64 c-partials (deterministic order).
// ---------------------------------------------------------------------------
__global__ void proto_prep(const float* __restrict__ mean,
                           const float* __restrict__ proj,
                           const float* __restrict__ proto) {
    const int b = blockIdx.x, t = threadIdx.x;
    if (b < 64) {
        __shared__ __nv_bfloat16 tile[16][258];   // +2 pad: kill bank conflicts
        const int r0 = b * 16;
        const int r = t >> 4, cq = (t & 15) * 16; // 16 thr/row, 16 cols each
        #pragma unroll
        for (int j = 0; j < 4; j++) {
            float4 v = *(const float4*)(proj + (size_t)(r0 + r) * D_PROJ + cq + 4 * j);
            tile[r][cq + 4 * j + 0] = __float2bfloat16(v.x);
            tile[r][cq + 4 * j + 1] = __float2bfloat16(v.y);
            tile[r][cq + 4 * j + 2] = __float2bfloat16(v.z);
            tile[r][cq + 4 * j + 3] = __float2bfloat16(v.w);
        }
        // partial c over this block's 16 d-rows (coalesced over t, L2-hot)
        float p0 = 0.f, p1 = 0.f, p2 = 0.f, p3 = 0.f;
        #pragma unroll
        for (int i = 0; i < 16; i += 4) {
            p0 = fmaf(mean[r0 + i],     proj[(size_t)(r0 + i)     * D_PROJ + t], p0);
            p1 = fmaf(mean[r0 + i + 1], proj[(size_t)(r0 + i + 1) * D_PROJ + t], p1);
            p2 = fmaf(mean[r0 + i + 2], proj[(size_t)(r0 + i + 2) * D_PROJ + t], p2);
            p3 = fmaf(mean[r0 + i + 3], proj[(size_t)(r0 + i + 3) * D_PROJ + t], p3);
        }
        g_cpart[b * D_PROJ + t] = (p0 + p1) + (p2 + p3);
        __syncthreads();
        // thread t owns output column t: writes 16 consecutive k's (32B)
        #pragma unroll
        for (int i = 0; i < 2; i++) {
            uint32_t w[4];
            #pragma unroll
            for (int j = 0; j < 4; j++) {
                __nv_bfloat162 pv;
                pv.x = tile[i * 8 + 2 * j][t];
                pv.y = tile[i * 8 + 2 * j + 1][t];
                w[j] = *(uint32_t*)&pv;
            }
            *(uint4*)&g_Bw[(size_t)t * D_IN + r0 + i * 8] =
                make_uint4(w[0], w[1], w[2], w[3]);
        }
    } else {
        // convert 16 proto rows + fused p2 (16 threads per row)
        const int row = (b - 64) * 16 + (t >> 4);
        const int seg = (t & 15) * 16;
        const float* p = proto + (size_t)row * D_PROJ + seg;
        float4 u = *(const float4*)(p);
        float4 v = *(const float4*)(p + 4);
        float4 x = *(const float4*)(p + 8);
        float4 y = *(const float4*)(p + 12);
        float ss = 0.f;
        ss = fmaf(u.x, u.x, fmaf(u.y, u.y, fmaf(u.z, u.z, fmaf(u.w, u.w, ss))));
        ss = fmaf(v.x, v.x, fmaf(v.y, v.y, fmaf(v.z, v.z, fmaf(v.w, v.w, ss))));
        ss = fmaf(x.x, x.x, fmaf(x.y, x.y, fmaf(x.z, x.z, fmaf(x.w, x.w, ss))));
        ss = fmaf(y.x, y.x, fmaf(y.y, y.y, fmaf(y.z, y.z, fmaf(y.w, y.w, ss))));
        __nv_bfloat162 w0 = __floats2bfloat162_rn(u.x, u.y);
        __nv_bfloat162 w1 = __floats2bfloat162_rn(u.z, u.w);
        __nv_bfloat162 w2 = __floats2bfloat162_rn(v.x, v.y);
        __nv_bfloat162 w3 = __floats2bfloat162_rn(v.z, v.w);
        *(uint4*)&g_Bp[(size_t)row * D_PROJ + seg] = make_uint4(
            *(uint32_t*)&w0, *(uint32_t*)&w1, *(uint32_t*)&w2, *(uint32_t*)&w3);
        __nv_bfloat162 w4 = __floats2bfloat162_rn(x.x, x.y);
        __nv_bfloat162 w5 = __floats2bfloat162_rn(x.z, x.w);
        __nv_bfloat162 w6 = __floats2bfloat162_rn(y.x, y.y);
        __nv_bfloat162 w7 = __floats2bfloat162_rn(y.z, y.w);
        *(uint4*)&g_Bp[(size_t)row * D_PROJ + seg + 8] = make_uint4(
            *(uint32_t*)&w4, *(uint32_t*)&w5, *(uint32_t*)&w6, *(uint32_t*)&w7);
        // fixed-tree reduction over the 16 lanes of this row (deterministic)
        ss += __shfl_xor_sync(0xffffffffu, ss, 1);
        ss += __shfl_xor_sync(0xffffffffu, ss, 2);
        ss += __shfl_xor_sync(0xffffffffu, ss, 4);
        ss += __shfl_xor_sync(0xffffffffu, ss, 8);
        if ((t & 15) == 0) g_p2[row] = ss;
    }
}

__global__ void proto_prep2() {
    const int t = threadIdx.x;
    float a0 = 0.f, a1 = 0.f, a2 = 0.f, a3 = 0.f;
    #pragma unroll
    for (int i = 0; i < 64; i += 4) {
        a0 += g_cpart[(i)     * D_PROJ + t];
        a1 += g_cpart[(i + 1) * D_PROJ + t];
        a2 += g_cpart[(i + 2) * D_PROJ + t];
        a3 += g_cpart[(i + 3) * D_PROJ + t];
    }
    g_c[t] = (a0 + a1) + (a2 + a3);
}

// ---------------------------------------------------------------------------
// Fused kernel: 256 CTAs x 512 threads (TM=128), 16 warps/SM.
// Warp grid 4(M) x 4(N), warp tile 32x64. 3-stage cp.async B pipeline.
// ---------------------------------------------------------------------------
__global__ void __launch_bounds__(512, 1) proto_fused(const float* __restrict__ X,
                                                      float* __restrict__ out) {
    extern __shared__ __align__(128) unsigned char smem[];
    const uint32_t sb = smem_u32(smem);
    const uint32_t sA = sb + OFF_A;
    const uint32_t sB = sb + OFF_B;
    const uint32_t sZ = sb + OFF_Z;
    const int tid = threadIdx.x, lane = tid & 31, wid = tid >> 5;
    const int wm = wid & 3, wn = wid >> 2;
    const int m0 = blockIdx.x * TM;

    // prefetch c / p2 into registers (consumed after the mainloop)
    float creg = 0.f, p2reg = 0.f;
    if (tid < 256) { creg = g_c[tid]; p2reg = g_p2[tid]; }

    float acc[2][8][4];
    #pragma unroll
    for (int a = 0; a < 2; a++)
        #pragma unroll
        for (int b = 0; b < 8; b++)
            #pragma unroll
            for (int c = 0; c < 4; c++) acc[a][b][c] = 0.f;

    // A (X f32 -> bf16): 128 rows x 16 float4; 512 thr -> 4 float4 each
    const int tx = tid & 15, ty = tid >> 4;          // ty in 0..31, rows ty+32i
    const float* gA = X + (size_t)(m0 + ty) * D_IN + tx * 4;
    const uint32_t stsAoff = (uint32_t)(ty * 128) + (uint32_t)((tx * 8) ^ ((ty & 7) << 4));
    // B streams: 256 rows x 8 x 16B; 512 thr -> 4 cp16 each (rows by+64i)
    const int bx = tid & 7, by = tid >> 3;           // by in 0..63
    const __nv_bfloat16* gBw = g_Bw + (size_t)by * D_IN + bx * 8;
    const __nv_bfloat16* gBp = g_Bp + (size_t)by * D_PROJ + bx * 8;
    const uint32_t cpBoff = (uint32_t)(by * 128) + (uint32_t)((bx * 16) ^ ((by & 7) << 4));

    float4 aR[4];
    // ---- phase 1 prologue: A0 + B0 + B1 ----
    #pragma unroll
    for (int i = 0; i < 4; i++) aR[i] = *(const float4*)(gA + (size_t)(32 * i) * D_IN);
    #pragma unroll
    for (int i = 0; i < 4; i++) cp16(sB + cpBoff + i * 64 * 128, gBw + (size_t)(64 * i) * D_IN);
    CP_COMMIT();
    #pragma unroll
    for (int i = 0; i < 4; i++)
        cp16(sB + 32768 + cpBoff + i * 64 * 128, gBw + (size_t)(64 * i) * D_IN + KT);
    CP_COMMIT();
    #pragma unroll
    for (int i = 0; i < 4; i++) {
        __nv_bfloat162 l2 = __floats2bfloat162_rn(aR[i].x, aR[i].y);
        __nv_bfloat162 h2 = __floats2bfloat162_rn(aR[i].z, aR[i].w);
        *(uint2*)(smem + OFF_A + stsAoff + i * 32 * 128) =
            make_uint2(*(uint32_t*)&l2, *(uint32_t*)&h2);
    }
    CP_WAIT1();          // B0 landed (B1 may be in flight)
    __syncthreads();

    // ---- phase 1 mainloop: 16 stages of K=64, 3-buffer rotation ----
    for (int kt = 0; kt < NS1; kt++) {
        const int cur = kt % 3;
        const bool moreA = (kt + 1) < NS1;
        const bool moreB = (kt + 2) < NS1;
        if (moreA) {
            const int kb = (kt + 1) * KT;
            #pragma unroll
            for (int i = 0; i < 4; i++)
                aR[i] = *(const float4*)(gA + (size_t)(32 * i) * D_IN + kb);
        }
        if (moreB) {
            const int kb = (kt + 2) * KT;
            const int nb = (kt + 2) % 3;
            #pragma unroll
            for (int i = 0; i < 4; i++)
                cp16(sB + nb * 32768 + cpBoff + i * 64 * 128,
                     gBw + (size_t)(64 * i) * D_IN + kb);
            CP_COMMIT();
        }
        mma_stage(sA + cur * 16384, sB + cur * 32768, lane, wm, wn, acc);
        if (moreA) {
            const int na = (kt + 1) % 3;
            #pragma unroll
            for (int i = 0; i < 4; i++) {
                __nv_bfloat162 l2 = __floats2bfloat162_rn(aR[i].x, aR[i].y);
                __nv_bfloat162 h2 = __floats2bfloat162_rn(aR[i].z, aR[i].w);
                *(uint2*)(smem + OFF_A + na * 16384 + stsAoff + i * 32 * 128) =
                    make_uint2(*(uint32_t*)&l2, *(uint32_t*)&h2);
            }
        }
        if (moreB) { CP_WAIT1(); } else { CP_WAIT0(); }
        __syncthreads();
    }

    // ---- prefetch prototype stages 0,1 (overlap with norm epilogue) ----
    #pragma unroll
    for (int i = 0; i < 4; i++)
        cp16(sB + cpBoff + i * 64 * 128, gBp + (size_t)(64 * i) * D_PROJ);
    CP_COMMIT();
    #pragma unroll
    for (int i = 0; i < 4; i++)
        cp16(sB + 32768 + cpBoff + i * 64 * 128, gBp + (size_t)(64 * i) * D_PROJ + KT);
    CP_COMMIT();

    // A buffers dead: reuse buf0 for c / p2 / red (stored from registers).
    float* cs  = (float*)(smem + OFF_C);
    float* p2s = (float*)(smem + OFF_P2);
    float* red = (float*)(smem + OFF_RED);
    if (tid < 256) { cs[tid] = creg; p2s[tid] = p2reg; }
    __syncthreads();

    // ---- norm epilogue: Y = acc - c, row norms, z -> smem Z panels (bf16) ----
    const int c0 = wn * 64 + 2 * (lane & 3);
    float s[2][2];
    #pragma unroll
    for (int mi = 0; mi < 2; mi++) { s[mi][0] = 0.f; s[mi][1] = 0.f; }
    #pragma unroll
    for (int mi = 0; mi < 2; mi++)
        #pragma unroll
        for (int ni = 0; ni < 8; ni++)
            #pragma unroll
            for (int j = 0; j < 4; j++) {
                float v = acc[mi][ni][j] - cs[c0 + ni * 8 + (j & 1)];
                acc[mi][ni][j] = v;
                s[mi][j >> 1] = fmaf(v, v, s[mi][j >> 1]);
            }
    #pragma unroll
    for (int mi = 0; mi < 2; mi++)
        #pragma unroll
        for (int h = 0; h < 2; h++) {
            s[mi][h] += __shfl_xor_sync(0xffffffffu, s[mi][h], 1);
            s[mi][h] += __shfl_xor_sync(0xffffffffu, s[mi][h], 2);
        }
    const int r0 = wm * 32 + (lane >> 2);
    if ((lane & 3) == 0) {
        #pragma unroll
        for (int mi = 0; mi < 2; mi++)
            #pragma unroll
            for (int h = 0; h < 2; h++)
                red[(r0 + mi * 16 + h * 8) * 4 + wn] = s[mi][h];
    }
    __syncthreads();
    // Z panel wn holds k in [wn*64, wn*64+64): 128 rows x 128B, swizzled
    #pragma unroll
    for (int mi = 0; mi < 2; mi++)
        #pragma unroll
        for (int h = 0; h < 2; h++) {
            const int r = r0 + mi * 16 + h * 8;
            float t = red[r * 4 + 0] + red[r * 4 + 1] + red[r * 4 + 2] + red[r * 4 + 3];
            float inv = 1.f / fmaxf(sqrtf(t), 1e-12f);
            const uint32_t zrow = sZ + (uint32_t)(wn * 16384 + r * 128);
            const uint32_t xr = (uint32_t)((r & 7) << 4);
            #pragma unroll
            for (int ni = 0; ni < 8; ni++) {
                __nv_bfloat162 zz = __floats2bfloat162_rn(acc[mi][ni][2 * h] * inv,
                                                          acc[mi][ni][2 * h + 1] * inv);
                const uint32_t boff = (uint32_t)((lane & 3) * 4 + ni * 16) ^ xr;
                asm volatile("st.shared.b32 [%0], %1;" :: "r"(zrow + boff),
                             "r"(*(uint32_t*)&zz) : "memory");
            }
        }

    // reuse acc for phase 2
    #pragma unroll
    for (int a = 0; a < 2; a++)
        #pragma unroll
        for (int b = 0; b < 8; b++)
            #pragma unroll
            for (int c = 0; c < 4; c++) acc[a][b][c] = 0.f;

    CP_WAIT1();        // prototype stage 0 landed
    __syncthreads();   // all Z panels visible

    // ---- phase 2: S = Z @ P^T over 4 k-stages (A = smem Z panels) ----
    for (int s2 = 0; s2 < NS2; s2++) {
        const bool moreB = (s2 + 2) < NS2;
        if (moreB) {
            const int nb = (s2 + 2) % 3;
            #pragma unroll
            for (int i = 0; i < 4; i++)
                cp16(sB + nb * 32768 + cpBoff + i * 64 * 128,
                     gBp + (size_t)(64 * i) * D_PROJ + (s2 + 2) * KT);
            CP_COMMIT();
        }
        mma_stage(sZ + s2 * 16384, sB + (s2 % 3) * 32768, lane, wm, wn, acc);
        if (moreB) { CP_WAIT1(); } else { CP_WAIT0(); }
        __syncthreads();
    }

    // ---- final epilogue: score = -sqrt(max(1 + p2 - 2 s, 0)) ----
    #pragma unroll
    for (int mi = 0; mi < 2; mi++)
        #pragma unroll
        for (int h = 0; h < 2; h++) {
            const size_t rowoff = (size_t)(m0 + r0 + mi * 16 + h * 8) * N_CLS;
            #pragma unroll
            for (int ni = 0; ni < 8; ni++) {
                const int cc = c0 + ni * 8;
                float2 v;
                v.x = -sqrtf(fmaxf(1.0f + p2s[cc]     - 2.f * acc[mi][ni][2 * h],     0.f));
                v.y = -sqrtf(fmaxf(1.0f + p2s[cc + 1] - 2.f * acc[mi][ni][2 * h + 1], 0.f));
                *(float2*)(out + rowoff + cc) = v;
            }
        }
}

// ---------------------------------------------------------------------------
// Host launcher (graph-capturable: kernel launches only)
// ---------------------------------------------------------------------------
extern "C" void kernel_launch(void* const* d_in, const int* in_sizes, int n_in,
                              void* d_out, int out_size) {
    const float* X     = (const float*)d_in[0];
    const float* mean  = (const float*)d_in[1];
    const float* proj  = (const float*)d_in[2];
    const float* proto = (const float*)d_in[3];
    float* out = (float*)d_out;

    cudaFuncSetAttribute(proto_fused, cudaFuncAttributeMaxDynamicSharedMemorySize, SMEMF);

    proto_prep<<<80, 256>>>(mean, proj, proto);
    proto_prep2<<<1, 256>>>();
    proto_fused<<<N_ROWS / TM, 512, SMEMF>>>(X, out);
}

// round 16
// speedup vs baseline: 1.0957x; 1.0957x over previous
#include <cuda_runtime.h>
#include <cuda_bf16.h>
#include <cstdint>
#include <cmath>

// ============================================================================
// ProtoNetLayer — fused single-pass mma.sync bf16 kernel (sm_103-family safe).
//
//   scores[n,c] = -sqrt(max(1 + |P_c|^2 - 2 * z_n . P_c, 0))
//   phase 1: Y = X @ projT^T - c   (K=1024, cp.async/ldmatrix/mma pipeline)
//   norm:    z = Y / max(|Y|,eps)  -> bf16 in shared memory
//   phase 2: S = z @ P^T (K=256, A from smem Z panels) + sqrt epilogue
//
// R15: R14's %3 rotation regressed fused ~70->88us (address math no longer
// constant-foldable + reg pressure). Rebuild on the R11 core with HALVED
// synchronization density instead:
//   - two K=64 sub-stages per barrier/wait/commit (4 A-bufs + 4 B-bufs, all
//     indices &3 with #pragma unroll 2 so addresses fold);
//   - phase 2 barrier-free: all 4 prototype stages prefetched into the 4 B
//     slots during the norm epilogue; 4 back-to-back mma_stages, no waits;
//   - Z overlays the dead A region; c/p2/red in a dedicated 4KB tail.
// ============================================================================

#define N_ROWS  32768
#define D_IN    1024
#define D_PROJ  256
#define N_CLS   256
#define TM      128
#define KT      64

// fused-kernel smem layout (bytes)
#define OFF_A    0        // A sub-buffers: 4 x 16384 (128 rows x 128B); Z after phase 1
#define OFF_B    65536    // B sub-buffers: 4 x 32768 (256 rows x 128B)
#define OFF_C    196608   // c[256] f32
#define OFF_P2   197632   // p2[256] f32
#define OFF_RED  198656   // red[128][4] f32
#define SMEMF    200704

// device-global scratch (no runtime allocation allowed)
__device__ __align__(256) __nv_bfloat16 g_Bw[D_PROJ * D_IN];   // projT bf16 [256][1024]
__device__ __align__(256) __nv_bfloat16 g_Bp[N_CLS * D_PROJ];  // prototypes bf16 [256][256]
__device__ float g_cpart[64 * D_PROJ];                         // partial c per transpose block
__device__ float g_c[D_PROJ];                                  // mean @ proj
__device__ float g_p2[N_CLS];                                  // |P_c|^2

// ---------------------------------------------------------------------------
// asm helpers (family-agnostic: sm_75/sm_80 features)
// ---------------------------------------------------------------------------
__device__ __forceinline__ uint32_t smem_u32(const void* p) {
    uint32_t a;
    asm("{ .reg .u64 t; cvta.to.shared.u64 t, %1; cvt.u32.u64 %0, t; }" : "=r"(a) : "l"(p));
    return a;
}
__device__ __forceinline__ void ldmx4(uint32_t* r, uint32_t a) {
    asm volatile("ldmatrix.sync.aligned.m8n8.x4.shared.b16 {%0,%1,%2,%3}, [%4];"
                 : "=r"(r[0]), "=r"(r[1]), "=r"(r[2]), "=r"(r[3]) : "r"(a));
}
__device__ __forceinline__ void mmabf16(float* c, const uint32_t* a, uint32_t b0, uint32_t b1) {
    asm volatile("mma.sync.aligned.m16n8k16.row.col.f32.bf16.bf16.f32 "
                 "{%0,%1,%2,%3}, {%4,%5,%6,%7}, {%8,%9}, {%0,%1,%2,%3};"
                 : "+f"(c[0]), "+f"(c[1]), "+f"(c[2]), "+f"(c[3])
                 : "r"(a[0]), "r"(a[1]), "r"(a[2]), "r"(a[3]), "r"(b0), "r"(b1));
}
__device__ __forceinline__ void cp16(uint32_t d, const void* s) {
    asm volatile("cp.async.cg.shared.global [%0], [%1], 16;" :: "r"(d), "l"(s) : "memory");
}
#define CP_COMMIT() asm volatile("cp.async.commit_group;" ::: "memory")
#define CP_WAIT0()  asm volatile("cp.async.wait_group 0;" ::: "memory")

// 32(M) x 64(N) warp-tile mma over one K=64 sub-stage (swizzled smem, 128B rows)
__device__ __forceinline__ void mma_stage(uint32_t Abase, uint32_t Bbase,
                                          int lane, int wm, int wn,
                                          float (&acc)[2][8][4]) {
    const int ra  = (lane & 7) + ((lane >> 3) & 1) * 8;
    const int kxa = ((lane >> 4) & 1) * 16;
    const int rb  = (lane & 7) + ((lane >> 4) & 1) * 8;
    const int kxb = ((lane >> 3) & 1) * 16;
    const int xa = (lane & 7) << 4;
    const uint32_t Aw = Abase + (uint32_t)(wm * 32 + ra) * 128;
    const uint32_t Bw = Bbase + (uint32_t)(wn * 64 + rb) * 128;
    #pragma unroll
    for (int k16 = 0; k16 < 4; k16++) {
        uint32_t aF[2][4], bF[4][4];
        #pragma unroll
        for (int mi = 0; mi < 2; mi++)
            ldmx4(aF[mi], Aw + mi * 16 * 128 + (uint32_t)((k16 * 32 + kxa) ^ xa));
        #pragma unroll
        for (int nj = 0; nj < 4; nj++)
            ldmx4(bF[nj], Bw + nj * 16 * 128 + (uint32_t)((k16 * 32 + kxb) ^ xa));
        #pragma unroll
        for (int mi = 0; mi < 2; mi++)
            #pragma unroll
            for (int nj = 0; nj < 4; nj++) {
                mmabf16(acc[mi][2 * nj],     aF[mi], bF[nj][0], bF[nj][1]);
                mmabf16(acc[mi][2 * nj + 1], aF[mi], bF[nj][2], bF[nj][3]);
            }
    }
}

// ---------------------------------------------------------------------------
// Prep (80 blocks x 256 threads) — unchanged from R14 (measured 5.9us):
//  blocks 0..63 : projT transpose tile (16 d-rows) + partial c
//  blocks 64..79: prototypes f32->bf16 convert (16 rows) + fused p2
// Then proto_prep2<<<1,256>>> folds the 64 c-partials (deterministic order).
// ---------------------------------------------------------------------------
__global__ void proto_prep(const float* __restrict__ mean,
                           const float* __restrict__ proj,
                           const float* __restrict__ proto) {
    const int b = blockIdx.x, t = threadIdx.x;
    if (b < 64) {
        __shared__ __nv_bfloat16 tile[16][258];
        const int r0 = b * 16;
        const int r = t >> 4, cq = (t & 15) * 16;
        #pragma unroll
        for (int j = 0; j < 4; j++) {
            float4 v = *(const float4*)(proj + (size_t)(r0 + r) * D_PROJ + cq + 4 * j);
            tile[r][cq + 4 * j + 0] = __float2bfloat16(v.x);
            tile[r][cq + 4 * j + 1] = __float2bfloat16(v.y);
            tile[r][cq + 4 * j + 2] = __float2bfloat16(v.z);
            tile[r][cq + 4 * j + 3] = __float2bfloat16(v.w);
        }
        float p0 = 0.f, p1 = 0.f, p2 = 0.f, p3 = 0.f;
        #pragma unroll
        for (int i = 0; i < 16; i += 4) {
            p0 = fmaf(mean[r0 + i],     proj[(size_t)(r0 + i)     * D_PROJ + t], p0);
            p1 = fmaf(mean[r0 + i + 1], proj[(size_t)(r0 + i + 1) * D_PROJ + t], p1);
            p2 = fmaf(mean[r0 + i + 2], proj[(size_t)(r0 + i + 2) * D_PROJ + t], p2);
            p3 = fmaf(mean[r0 + i + 3], proj[(size_t)(r0 + i + 3) * D_PROJ + t], p3);
        }
        g_cpart[b * D_PROJ + t] = (p0 + p1) + (p2 + p3);
        __syncthreads();
        #pragma unroll
        for (int i = 0; i < 2; i++) {
            uint32_t w[4];
            #pragma unroll
            for (int j = 0; j < 4; j++) {
                __nv_bfloat162 pv;
                pv.x = tile[i * 8 + 2 * j][t];
                pv.y = tile[i * 8 + 2 * j + 1][t];
                w[j] = *(uint32_t*)&pv;
            }
            *(uint4*)&g_Bw[(size_t)t * D_IN + r0 + i * 8] =
                make_uint4(w[0], w[1], w[2], w[3]);
        }
    } else {
        const int row = (b - 64) * 16 + (t >> 4);
        const int seg = (t & 15) * 16;
        const float* p = proto + (size_t)row * D_PROJ + seg;
        float4 u = *(const float4*)(p);
        float4 v = *(const float4*)(p + 4);
        float4 x = *(const float4*)(p + 8);
        float4 y = *(const float4*)(p + 12);
        float ss = 0.f;
        ss = fmaf(u.x, u.x, fmaf(u.y, u.y, fmaf(u.z, u.z, fmaf(u.w, u.w, ss))));
        ss = fmaf(v.x, v.x, fmaf(v.y, v.y, fmaf(v.z, v.z, fmaf(v.w, v.w, ss))));
        ss = fmaf(x.x, x.x, fmaf(x.y, x.y, fmaf(x.z, x.z, fmaf(x.w, x.w, ss))));
        ss = fmaf(y.x, y.x, fmaf(y.y, y.y, fmaf(y.z, y.z, fmaf(y.w, y.w, ss))));
        __nv_bfloat162 w0 = __floats2bfloat162_rn(u.x, u.y);
        __nv_bfloat162 w1 = __floats2bfloat162_rn(u.z, u.w);
        __nv_bfloat162 w2 = __floats2bfloat162_rn(v.x, v.y);
        __nv_bfloat162 w3 = __floats2bfloat162_rn(v.z, v.w);
        *(uint4*)&g_Bp[(size_t)row * D_PROJ + seg] = make_uint4(
            *(uint32_t*)&w0, *(uint32_t*)&w1, *(uint32_t*)&w2, *(uint32_t*)&w3);
        __nv_bfloat162 w4 = __floats2bfloat162_rn(x.x, x.y);
        __nv_bfloat162 w5 = __floats2bfloat162_rn(x.z, x.w);
        __nv_bfloat162 w6 = __floats2bfloat162_rn(y.x, y.y);
        __nv_bfloat162 w7 = __floats2bfloat162_rn(y.z, y.w);
        *(uint4*)&g_Bp[(size_t)row * D_PROJ + seg + 8] = make_uint4(
            *(uint32_t*)&w4, *(uint32_t*)&w5, *(uint32_t*)&w6, *(uint32_t*)&w7);
        ss += __shfl_xor_sync(0xffffffffu, ss, 1);
        ss += __shfl_xor_sync(0xffffffffu, ss, 2);
        ss += __shfl_xor_sync(0xffffffffu, ss, 4);
        ss += __shfl_xor_sync(0xffffffffu, ss, 8);
        if ((t & 15) == 0) g_p2[row] = ss;
    }
}

__global__ void proto_prep2() {
    const int t = threadIdx.x;
    float a0 = 0.f, a1 = 0.f, a2 = 0.f, a3 = 0.f;
    #pragma unroll
    for (int i = 0; i < 64; i += 4) {
        a0 += g_cpart[(i)     * D_PROJ + t];
        a1 += g_cpart[(i + 1) * D_PROJ + t];
        a2 += g_cpart[(i + 2) * D_PROJ + t];
        a3 += g_cpart[(i + 3) * D_PROJ + t];
    }
    g_c[t] = (a0 + a1) + (a2 + a3);
}

// ---------------------------------------------------------------------------
// Fused kernel: 256 CTAs x 512 threads (TM=128), 16 warps/SM.
// Warp grid 4(M) x 4(N), warp tile 32x64. Paired K-stages: one barrier /
// wait / commit per TWO K=64 sub-stages. Phase 2 barrier-free.
// ---------------------------------------------------------------------------
__global__ void __launch_bounds__(512, 1) proto_fused(const float* __restrict__ X,
                                                      float* __restrict__ out) {
    extern __shared__ __align__(128) unsigned char smem[];
    const uint32_t sb = smem_u32(smem);
    const uint32_t sA = sb + OFF_A;      // also the Z region after phase 1
    const uint32_t sB = sb + OFF_B;
    const int tid = threadIdx.x, lane = tid & 31, wid = tid >> 5;
    const int wm = wid & 3, wn = wid >> 2;
    const int m0 = blockIdx.x * TM;

    // prefetch c / p2 into registers (consumed after the mainloop)
    float creg = 0.f, p2reg = 0.f;
    if (tid < 256) { creg = g_c[tid]; p2reg = g_p2[tid]; }

    float acc[2][8][4];
    #pragma unroll
    for (int a = 0; a < 2; a++)
        #pragma unroll
        for (int b = 0; b < 8; b++)
            #pragma unroll
            for (int c = 0; c < 4; c++) acc[a][b][c] = 0.f;

    // A (X f32 -> bf16): 128 rows x 16 float4; 512 thr -> 4 float4 per sub-stage
    const int tx = tid & 15, ty = tid >> 4;
    const float* gA = X + (size_t)(m0 + ty) * D_IN + tx * 4;
    const uint32_t stsAoff = (uint32_t)(ty * 128) + (uint32_t)((tx * 8) ^ ((ty & 7) << 4));
    // B streams: 256 rows x 8 x 16B; 512 thr -> 4 cp16 per sub-stage
    const int bx = tid & 7, by = tid >> 3;
    const __nv_bfloat16* gBw = g_Bw + (size_t)by * D_IN + bx * 8;
    const __nv_bfloat16* gBp = g_Bp + (size_t)by * D_PROJ + bx * 8;
    const uint32_t cpBoff = (uint32_t)(by * 128) + (uint32_t)((bx * 16) ^ ((by & 7) << 4));

    float4 aR[4];
    // ---- prologue: A subs 0,1 (LDG+convert+STS) and B pair 0 (one group) ----
    #pragma unroll
    for (int i = 0; i < 4; i++) aR[i] = *(const float4*)(gA + (size_t)(32 * i) * D_IN);
    #pragma unroll
    for (int i = 0; i < 4; i++) cp16(sB + cpBoff + i * 64 * 128, gBw + (size_t)(64 * i) * D_IN);
    #pragma unroll
    for (int i = 0; i < 4; i++)
        cp16(sB + 32768 + cpBoff + i * 64 * 128, gBw + (size_t)(64 * i) * D_IN + KT);
    CP_COMMIT();
    #pragma unroll
    for (int i = 0; i < 4; i++) {
        __nv_bfloat162 l2 = __floats2bfloat162_rn(aR[i].x, aR[i].y);
        __nv_bfloat162 h2 = __floats2bfloat162_rn(aR[i].z, aR[i].w);
        *(uint2*)(smem + OFF_A + stsAoff + i * 32 * 128) =
            make_uint2(*(uint32_t*)&l2, *(uint32_t*)&h2);
    }
    #pragma unroll
    for (int i = 0; i < 4; i++) aR[i] = *(const float4*)(gA + (size_t)(32 * i) * D_IN + KT);
    #pragma unroll
    for (int i = 0; i < 4; i++) {
        __nv_bfloat162 l2 = __floats2bfloat162_rn(aR[i].x, aR[i].y);
        __nv_bfloat162 h2 = __floats2bfloat162_rn(aR[i].z, aR[i].w);
        *(uint2*)(smem + OFF_A + 16384 + stsAoff + i * 32 * 128) =
            make_uint2(*(uint32_t*)&l2, *(uint32_t*)&h2);
    }

    // ---- phase 1: 8 pairs of K=64 sub-stages; 1 barrier+1 wait+1 commit/pair.
    // Sub-stage s uses A slot (s&3)*16384 and B slot (s&3)*32768.
    #pragma unroll 2
    for (int p = 0; p < 8; p++) {
        const int s0 = (2 * p) & 3, s1 = (2 * p + 1) & 3;
        const int n0 = (2 * p + 2) & 3, n1 = (2 * p + 3) & 3;
        const bool more = (p + 1) < 8;
        CP_WAIT0();          // this pair's B landed (own group)
        __syncthreads();     // all threads' B landed; prior pair's reads done
        if (more) {
            const int kb = (2 * p + 2) * KT;
            #pragma unroll
            for (int i = 0; i < 4; i++)
                cp16(sB + n0 * 32768 + cpBoff + i * 64 * 128,
                     gBw + (size_t)(64 * i) * D_IN + kb);
            #pragma unroll
            for (int i = 0; i < 4; i++)
                cp16(sB + n1 * 32768 + cpBoff + i * 64 * 128,
                     gBw + (size_t)(64 * i) * D_IN + kb + KT);
            CP_COMMIT();
            #pragma unroll
            for (int i = 0; i < 4; i++)
                aR[i] = *(const float4*)(gA + (size_t)(32 * i) * D_IN + kb);
        }
        mma_stage(sA + s0 * 16384, sB + s0 * 32768, lane, wm, wn, acc);
        if (more) {
            #pragma unroll
            for (int i = 0; i < 4; i++) {
                __nv_bfloat162 l2 = __floats2bfloat162_rn(aR[i].x, aR[i].y);
                __nv_bfloat162 h2 = __floats2bfloat162_rn(aR[i].z, aR[i].w);
                *(uint2*)(smem + OFF_A + n0 * 16384 + stsAoff + i * 32 * 128) =
                    make_uint2(*(uint32_t*)&l2, *(uint32_t*)&h2);
            }
            const int kb = (2 * p + 3) * KT;
            #pragma unroll
            for (int i = 0; i < 4; i++)
                aR[i] = *(const float4*)(gA + (size_t)(32 * i) * D_IN + kb);
        }
        mma_stage(sA + s1 * 16384, sB + s1 * 32768, lane, wm, wn, acc);
        if (more) {
            #pragma unroll
            for (int i = 0; i < 4; i++) {
                __nv_bfloat162 l2 = __floats2bfloat162_rn(aR[i].x, aR[i].y);
                __nv_bfloat162 h2 = __floats2bfloat162_rn(aR[i].z, aR[i].w);
                *(uint2*)(smem + OFF_A + n1 * 16384 + stsAoff + i * 32 * 128) =
                    make_uint2(*(uint32_t*)&l2, *(uint32_t*)&h2);
            }
        }
    }

    // ---- phase transition ----
    __syncthreads();   // all warps done reading every A/B slot
    // prefetch ALL 4 prototype stages into the 4 B slots (one group)
    #pragma unroll
    for (int s = 0; s < 4; s++)
        #pragma unroll
        for (int i = 0; i < 4; i++)
            cp16(sB + s * 32768 + cpBoff + i * 64 * 128,
                 gBp + (size_t)(64 * i) * D_PROJ + s * KT);
    CP_COMMIT();
    float* cs  = (float*)(smem + OFF_C);
    float* p2s = (float*)(smem + OFF_P2);
    float* red = (float*)(smem + OFF_RED);
    if (tid < 256) { cs[tid] = creg; p2s[tid] = p2reg; }
    __syncthreads();   // cs/p2s visible

    // ---- norm epilogue: Y = acc - c, row norms, z -> Z panels in A region ----
    const int c0 = wn * 64 + 2 * (lane & 3);
    float s[2][2];
    #pragma unroll
    for (int mi = 0; mi < 2; mi++) { s[mi][0] = 0.f; s[mi][1] = 0.f; }
    #pragma unroll
    for (int mi = 0; mi < 2; mi++)
        #pragma unroll
        for (int ni = 0; ni < 8; ni++)
            #pragma unroll
            for (int j = 0; j < 4; j++) {
                float v = acc[mi][ni][j] - cs[c0 + ni * 8 + (j & 1)];
                acc[mi][ni][j] = v;
                s[mi][j >> 1] = fmaf(v, v, s[mi][j >> 1]);
            }
    #pragma unroll
    for (int mi = 0; mi < 2; mi++)
        #pragma unroll
        for (int h = 0; h < 2; h++) {
            s[mi][h] += __shfl_xor_sync(0xffffffffu, s[mi][h], 1);
            s[mi][h] += __shfl_xor_sync(0xffffffffu, s[mi][h], 2);
        }
    const int r0 = wm * 32 + (lane >> 2);
    if ((lane & 3) == 0) {
        #pragma unroll
        for (int mi = 0; mi < 2; mi++)
            #pragma unroll
            for (int h = 0; h < 2; h++)
                red[(r0 + mi * 16 + h * 8) * 4 + wn] = s[mi][h];
    }
    __syncthreads();
    // Z panel wn holds k in [wn*64, wn*64+64): 128 rows x 128B, swizzled
    #pragma unroll
    for (int mi = 0; mi < 2; mi++)
        #pragma unroll
        for (int h = 0; h < 2; h++) {
            const int r = r0 + mi * 16 + h * 8;
            float t = red[r * 4 + 0] + red[r * 4 + 1] + red[r * 4 + 2] + red[r * 4 + 3];
            float inv = 1.f / fmaxf(sqrtf(t), 1e-12f);
            const uint32_t zrow = sA + (uint32_t)(wn * 16384 + r * 128);
            const uint32_t xr = (uint32_t)((r & 7) << 4);
            #pragma unroll
            for (int ni = 0; ni < 8; ni++) {
                __nv_bfloat162 zz = __floats2bfloat162_rn(acc[mi][ni][2 * h] * inv,
                                                          acc[mi][ni][2 * h + 1] * inv);
                const uint32_t boff = (uint32_t)((lane & 3) * 4 + ni * 16) ^ xr;
                asm volatile("st.shared.b32 [%0], %1;" :: "r"(zrow + boff),
                             "r"(*(uint32_t*)&zz) : "memory");
            }
        }

    // reuse acc for phase 2
    #pragma unroll
    for (int a = 0; a < 2; a++)
        #pragma unroll
        for (int b = 0; b < 8; b++)
            #pragma unroll
            for (int c = 0; c < 4; c++) acc[a][b][c] = 0.f;

    CP_WAIT0();        // prototype stages 0-3 landed (own group)
    __syncthreads();   // Z panels + all threads' proto data visible

    // ---- phase 2: S = Z @ P^T, 4 stages, NO barriers/waits (read-only) ----
    #pragma unroll
    for (int s2 = 0; s2 < 4; s2++)
        mma_stage(sA + s2 * 16384, sB + s2 * 32768, lane, wm, wn, acc);

    // ---- final epilogue: score = -sqrt(max(1 + p2 - 2 s, 0)) ----
    #pragma unroll
    for (int mi = 0; mi < 2; mi++)
        #pragma unroll
        for (int h = 0; h < 2; h++) {
            const size_t rowoff = (size_t)(m0 + r0 + mi * 16 + h * 8) * N_CLS;
            #pragma unroll
            for (int ni = 0; ni < 8; ni++) {
                const int cc = c0 + ni * 8;
                float2 v;
                v.x = -sqrtf(fmaxf(1.0f + p2s[cc]     - 2.f * acc[mi][ni][2 * h],     0.f));
                v.y = -sqrtf(fmaxf(1.0f + p2s[cc + 1] - 2.f * acc[mi][ni][2 * h + 1], 0.f));
                *(float2*)(out + rowoff + cc) = v;
            }
        }
}

// ---------------------------------------------------------------------------
// Host launcher (graph-capturable: kernel launches only)
// ---------------------------------------------------------------------------
extern "C" void kernel_launch(void* const* d_in, const int* in_sizes, int n_in,
                              void* d_out, int out_size) {
    const float* X     = (const float*)d_in[0];
    const float* mean  = (const float*)d_in[1];
    const float* proj  = (const float*)d_in[2];
    const float* proto = (const float*)d_in[3];
    float* out = (float*)d_out;

    cudaFuncSetAttribute(proto_fused, cudaFuncAttributeMaxDynamicSharedMemorySize, SMEMF);

    proto_prep<<<80, 256>>>(mean, proj, proto);
    proto_prep2<<<1, 256>>>();
    proto_fused<<<N_ROWS / TM, 512, SMEMF>>>(X, out);
}

// round 17
// speedup vs baseline: 1.2533x; 1.1439x over previous
#include <cuda_runtime.h>
#include <cuda_bf16.h>
#include <cstdint>
#include <cmath>

// ============================================================================
// ProtoNetLayer — fused single-pass mma.sync bf16 kernel (sm_103-family safe).
//
//   scores[n,c] = -sqrt(max(1 + |P_c|^2 - 2 * z_n . P_c, 0))
//   phase 1: Y = X @ projT^T - c   (K=1024, cp.async/ldmatrix/mma pipeline)
//   norm:    z = Y / max(|Y|,eps)  -> bf16 in shared memory
//   phase 2: S = z @ P^T (K=256, A from smem Z panels) + sqrt epilogue
//
// R17: controlled comparison R11(160KB)=~70us-fused vs R14/R16(200-208KB)=
// ~80-88us-fused confirms the L1-carveout hypothesis: smem >~164KB starves
// L1 for the X-LDG + ldsm streams. Revert fused to the EXACT R11 body
// (2-buffer, 160KB). Keep the two verified wins: R14 prep (5.9us) and
// prep2 folded into fused (per-CTA 64-partial c-reduction overlapped with
// the prologue's B0 landing — one fewer launch).
// ============================================================================

#define N_ROWS  32768
#define D_IN    1024
#define D_PROJ  256
#define N_CLS   256
#define TM      128
#define KT      64

// fused-kernel smem layout (bytes) — R11 layout, 160KB
#define OFF_A    0        // phase1 A stages: 2 x 16384  (128 rows x 128B)
#define OFF_B    32768    // B stages: 2 x 32768         (256 rows x 128B)
#define OFF_Z    98304    // Z panels: 4 x 16384         (128 rows x 128B)
#define SMEMF    163840
// reuse of dead A-buf0 after phase-1 mainloop:
#define OFF_C    0        // c[256] f32
#define OFF_P2   1024     // p2[256] f32
#define OFF_RED  2048     // red[128][4] f32

// device-global scratch (no runtime allocation allowed)
__device__ __align__(256) __nv_bfloat16 g_Bw[D_PROJ * D_IN];   // projT bf16 [256][1024]
__device__ __align__(256) __nv_bfloat16 g_Bp[N_CLS * D_PROJ];  // prototypes bf16 [256][256]
__device__ float g_cpart[64 * D_PROJ];                         // partial c per transpose block
__device__ float g_p2[N_CLS];                                  // |P_c|^2

// ---------------------------------------------------------------------------
// asm helpers (family-agnostic: sm_75/sm_80 features)
// ---------------------------------------------------------------------------
__device__ __forceinline__ uint32_t smem_u32(const void* p) {
    uint32_t a;
    asm("{ .reg .u64 t; cvta.to.shared.u64 t, %1; cvt.u32.u64 %0, t; }" : "=r"(a) : "l"(p));
    return a;
}
__device__ __forceinline__ void ldmx4(uint32_t* r, uint32_t a) {
    asm volatile("ldmatrix.sync.aligned.m8n8.x4.shared.b16 {%0,%1,%2,%3}, [%4];"
                 : "=r"(r[0]), "=r"(r[1]), "=r"(r[2]), "=r"(r[3]) : "r"(a));
}
__device__ __forceinline__ void mmabf16(float* c, const uint32_t* a, uint32_t b0, uint32_t b1) {
    asm volatile("mma.sync.aligned.m16n8k16.row.col.f32.bf16.bf16.f32 "
                 "{%0,%1,%2,%3}, {%4,%5,%6,%7}, {%8,%9}, {%0,%1,%2,%3};"
                 : "+f"(c[0]), "+f"(c[1]), "+f"(c[2]), "+f"(c[3])
                 : "r"(a[0]), "r"(a[1]), "r"(a[2]), "r"(a[3]), "r"(b0), "r"(b1));
}
__device__ __forceinline__ void cp16(uint32_t d, const void* s) {
    asm volatile("cp.async.cg.shared.global [%0], [%1], 16;" :: "r"(d), "l"(s) : "memory");
}
#define CP_COMMIT() asm volatile("cp.async.commit_group;" ::: "memory")
#define CP_WAIT0()  asm volatile("cp.async.wait_group 0;" ::: "memory")

// 32(M) x 64(N) warp-tile mma over one K=64 stage (swizzled smem, 128B rows)
__device__ __forceinline__ void mma_stage(uint32_t Abase, uint32_t Bbase,
                                          int lane, int wm, int wn,
                                          float (&acc)[2][8][4]) {
    const int ra  = (lane & 7) + ((lane >> 3) & 1) * 8;
    const int kxa = ((lane >> 4) & 1) * 16;
    const int rb  = (lane & 7) + ((lane >> 4) & 1) * 8;
    const int kxb = ((lane >> 3) & 1) * 16;
    const int xa = (lane & 7) << 4;
    const uint32_t Aw = Abase + (uint32_t)(wm * 32 + ra) * 128;
    const uint32_t Bw = Bbase + (uint32_t)(wn * 64 + rb) * 128;
    #pragma unroll
    for (int k16 = 0; k16 < 4; k16++) {
        uint32_t aF[2][4], bF[4][4];
        #pragma unroll
        for (int mi = 0; mi < 2; mi++)
            ldmx4(aF[mi], Aw + mi * 16 * 128 + (uint32_t)((k16 * 32 + kxa) ^ xa));
        #pragma unroll
        for (int nj = 0; nj < 4; nj++)
            ldmx4(bF[nj], Bw + nj * 16 * 128 + (uint32_t)((k16 * 32 + kxb) ^ xa));
        #pragma unroll
        for (int mi = 0; mi < 2; mi++)
            #pragma unroll
            for (int nj = 0; nj < 4; nj++) {
                mmabf16(acc[mi][2 * nj],     aF[mi], bF[nj][0], bF[nj][1]);
                mmabf16(acc[mi][2 * nj + 1], aF[mi], bF[nj][2], bF[nj][3]);
            }
    }
}

// ---------------------------------------------------------------------------
// Prep (80 blocks x 256 threads) — measured 5.9us:
//  blocks 0..63 : projT transpose tile (16 d-rows) + partial c
//  blocks 64..79: prototypes f32->bf16 convert (16 rows) + fused p2
// The 64 c-partials are folded by each fused CTA (deterministic order).
// ---------------------------------------------------------------------------
__global__ void proto_prep(const float* __restrict__ mean,
                           const float* __restrict__ proj,
                           const float* __restrict__ proto) {
    const int b = blockIdx.x, t = threadIdx.x;
    if (b < 64) {
        __shared__ __nv_bfloat16 tile[16][258];
        const int r0 = b * 16;
        const int r = t >> 4, cq = (t & 15) * 16;
        #pragma unroll
        for (int j = 0; j < 4; j++) {
            float4 v = *(const float4*)(proj + (size_t)(r0 + r) * D_PROJ + cq + 4 * j);
            tile[r][cq + 4 * j + 0] = __float2bfloat16(v.x);
            tile[r][cq + 4 * j + 1] = __float2bfloat16(v.y);
            tile[r][cq + 4 * j + 2] = __float2bfloat16(v.z);
            tile[r][cq + 4 * j + 3] = __float2bfloat16(v.w);
        }
        float p0 = 0.f, p1 = 0.f, p2 = 0.f, p3 = 0.f;
        #pragma unroll
        for (int i = 0; i < 16; i += 4) {
            p0 = fmaf(mean[r0 + i],     proj[(size_t)(r0 + i)     * D_PROJ + t], p0);
            p1 = fmaf(mean[r0 + i + 1], proj[(size_t)(r0 + i + 1) * D_PROJ + t], p1);
            p2 = fmaf(mean[r0 + i + 2], proj[(size_t)(r0 + i + 2) * D_PROJ + t], p2);
            p3 = fmaf(mean[r0 + i + 3], proj[(size_t)(r0 + i + 3) * D_PROJ + t], p3);
        }
        g_cpart[b * D_PROJ + t] = (p0 + p1) + (p2 + p3);
        __syncthreads();
        #pragma unroll
        for (int i = 0; i < 2; i++) {
            uint32_t w[4];
            #pragma unroll
            for (int j = 0; j < 4; j++) {
                __nv_bfloat162 pv;
                pv.x = tile[i * 8 + 2 * j][t];
                pv.y = tile[i * 8 + 2 * j + 1][t];
                w[j] = *(uint32_t*)&pv;
            }
            *(uint4*)&g_Bw[(size_t)t * D_IN + r0 + i * 8] =
                make_uint4(w[0], w[1], w[2], w[3]);
        }
    } else {
        const int row = (b - 64) * 16 + (t >> 4);
        const int seg = (t & 15) * 16;
        const float* p = proto + (size_t)row * D_PROJ + seg;
        float4 u = *(const float4*)(p);
        float4 v = *(const float4*)(p + 4);
        float4 x = *(const float4*)(p + 8);
        float4 y = *(const float4*)(p + 12);
        float ss = 0.f;
        ss = fmaf(u.x, u.x, fmaf(u.y, u.y, fmaf(u.z, u.z, fmaf(u.w, u.w, ss))));
        ss = fmaf(v.x, v.x, fmaf(v.y, v.y, fmaf(v.z, v.z, fmaf(v.w, v.w, ss))));
        ss = fmaf(x.x, x.x, fmaf(x.y, x.y, fmaf(x.z, x.z, fmaf(x.w, x.w, ss))));
        ss = fmaf(y.x, y.x, fmaf(y.y, y.y, fmaf(y.z, y.z, fmaf(y.w, y.w, ss))));
        __nv_bfloat162 w0 = __floats2bfloat162_rn(u.x, u.y);
        __nv_bfloat162 w1 = __floats2bfloat162_rn(u.z, u.w);
        __nv_bfloat162 w2 = __floats2bfloat162_rn(v.x, v.y);
        __nv_bfloat162 w3 = __floats2bfloat162_rn(v.z, v.w);
        *(uint4*)&g_Bp[(size_t)row * D_PROJ + seg] = make_uint4(
            *(uint32_t*)&w0, *(uint32_t*)&w1, *(uint32_t*)&w2, *(uint32_t*)&w3);
        __nv_bfloat162 w4 = __floats2bfloat162_rn(x.x, x.y);
        __nv_bfloat162 w5 = __floats2bfloat162_rn(x.z, x.w);
        __nv_bfloat162 w6 = __floats2bfloat162_rn(y.x, y.y);
        __nv_bfloat162 w7 = __floats2bfloat162_rn(y.z, y.w);
        *(uint4*)&g_Bp[(size_t)row * D_PROJ + seg + 8] = make_uint4(
            *(uint32_t*)&w4, *(uint32_t*)&w5, *(uint32_t*)&w6, *(uint32_t*)&w7);
        ss += __shfl_xor_sync(0xffffffffu, ss, 1);
        ss += __shfl_xor_sync(0xffffffffu, ss, 2);
        ss += __shfl_xor_sync(0xffffffffu, ss, 4);
        ss += __shfl_xor_sync(0xffffffffu, ss, 8);
        if ((t & 15) == 0) g_p2[row] = ss;
    }
}

// ---------------------------------------------------------------------------
// Fused kernel: 256 CTAs x 512 threads (TM=128), 16 warps/SM — R11 body.
// Warp grid 4(M) x 4(N), warp tile 32x64, double-buffered cp.async.
// ---------------------------------------------------------------------------
__global__ void __launch_bounds__(512, 1) proto_fused(const float* __restrict__ X,
                                                      float* __restrict__ out) {
    extern __shared__ __align__(128) unsigned char smem[];
    const uint32_t sb = smem_u32(smem);
    const uint32_t sA = sb + OFF_A;
    const uint32_t sB = sb + OFF_B;
    const uint32_t sZ = sb + OFF_Z;
    const int tid = threadIdx.x, lane = tid & 31, wid = tid >> 5;
    const int wm = wid & 3, wn = wid >> 2;
    const int m0 = blockIdx.x * TM;

    float p2reg = 0.f;
    if (tid < 256) p2reg = g_p2[tid];

    float acc[2][8][4];
    #pragma unroll
    for (int a = 0; a < 2; a++)
        #pragma unroll
        for (int b = 0; b < 8; b++)
            #pragma unroll
            for (int c = 0; c < 4; c++) acc[a][b][c] = 0.f;

    // A (X f32 -> bf16): 128 rows x 16 float4; 512 thr -> 4 float4 each
    const int tx = tid & 15, ty = tid >> 4;          // ty in 0..31, rows ty+32i
    const float* gA = X + (size_t)(m0 + ty) * D_IN + tx * 4;
    const uint32_t stsAoff = (uint32_t)(ty * 128) + (uint32_t)((tx * 8) ^ ((ty & 7) << 4));
    // B streams: 256 rows x 8 x 16B; 512 thr -> 4 cp16 each (rows by+64i)
    const int bx = tid & 7, by = tid >> 3;           // by in 0..63
    const __nv_bfloat16* gBw = g_Bw + (size_t)by * D_IN + bx * 8;
    const __nv_bfloat16* gBp = g_Bp + (size_t)by * D_PROJ + bx * 8;
    const uint32_t cpBoff = (uint32_t)(by * 128) + (uint32_t)((bx * 16) ^ ((by & 7) << 4));

    float4 aR[4];
    // ---- phase 1 prologue: stage 0 ----
    #pragma unroll
    for (int i = 0; i < 4; i++) aR[i] = *(const float4*)(gA + (size_t)(32 * i) * D_IN);
    #pragma unroll
    for (int i = 0; i < 4; i++) cp16(sB + cpBoff + i * 64 * 128, gBw + (size_t)(64 * i) * D_IN);
    CP_COMMIT();
    #pragma unroll
    for (int i = 0; i < 4; i++) {
        __nv_bfloat162 l2 = __floats2bfloat162_rn(aR[i].x, aR[i].y);
        __nv_bfloat162 h2 = __floats2bfloat162_rn(aR[i].z, aR[i].w);
        *(uint2*)(smem + OFF_A + stsAoff + i * 32 * 128) =
            make_uint2(*(uint32_t*)&l2, *(uint32_t*)&h2);
    }
    // folded prep2: c = sum of 64 partials (L2-hot; hides under B0 landing)
    float creg = 0.f;
    if (tid < 256) {
        float a0 = 0.f, a1 = 0.f, a2 = 0.f, a3 = 0.f;
        #pragma unroll 4
        for (int i = 0; i < 64; i += 4) {
            a0 += g_cpart[(i)     * D_PROJ + tid];
            a1 += g_cpart[(i + 1) * D_PROJ + tid];
            a2 += g_cpart[(i + 2) * D_PROJ + tid];
            a3 += g_cpart[(i + 3) * D_PROJ + tid];
        }
        creg = (a0 + a1) + (a2 + a3);
    }
    CP_WAIT0();
    __syncthreads();

    // ---- phase 1 mainloop: 16 stages of K=64 ----
    for (int kt = 0; kt < D_IN / KT; kt++) {
        const int cur = kt & 1, nxt = cur ^ 1;
        const bool more = (kt + 1) < (D_IN / KT);
        if (more) {
            const int kb = (kt + 1) * KT;
            #pragma unroll
            for (int i = 0; i < 4; i++)
                aR[i] = *(const float4*)(gA + (size_t)(32 * i) * D_IN + kb);
            #pragma unroll
            for (int i = 0; i < 4; i++)
                cp16(sB + nxt * 32768 + cpBoff + i * 64 * 128,
                     gBw + (size_t)(64 * i) * D_IN + kb);
            CP_COMMIT();
        }
        mma_stage(sA + cur * 16384, sB + cur * 32768, lane, wm, wn, acc);
        if (more) {
            #pragma unroll
            for (int i = 0; i < 4; i++) {
                __nv_bfloat162 l2 = __floats2bfloat162_rn(aR[i].x, aR[i].y);
                __nv_bfloat162 h2 = __floats2bfloat162_rn(aR[i].z, aR[i].w);
                *(uint2*)(smem + OFF_A + nxt * 16384 + stsAoff + i * 32 * 128) =
                    make_uint2(*(uint32_t*)&l2, *(uint32_t*)&h2);
            }
            CP_WAIT0();
        }
        __syncthreads();
    }

    // A buffers dead: reuse buf0 for c / p2 / red (stored from registers).
    float* cs  = (float*)(smem + OFF_C);
    float* p2s = (float*)(smem + OFF_P2);
    float* red = (float*)(smem + OFF_RED);
    if (tid < 256) { cs[tid] = creg; p2s[tid] = p2reg; }

    // Prefetch prototype stage 0 into B buf0 (last phase-1 stage read buf1);
    // overlaps gmem latency with the norm epilogue.
    #pragma unroll
    for (int i = 0; i < 4; i++)
        cp16(sB + cpBoff + i * 64 * 128, gBp + (size_t)(64 * i) * D_PROJ);
    CP_COMMIT();
    __syncthreads();   // cs/p2s visible

    // ---- norm epilogue: Y = acc - c, row norms, z -> smem Z panels (bf16) ----
    const int c0 = wn * 64 + 2 * (lane & 3);
    float s[2][2];
    #pragma unroll
    for (int mi = 0; mi < 2; mi++) { s[mi][0] = 0.f; s[mi][1] = 0.f; }
    #pragma unroll
    for (int mi = 0; mi < 2; mi++)
        #pragma unroll
        for (int ni = 0; ni < 8; ni++)
            #pragma unroll
            for (int j = 0; j < 4; j++) {
                float v = acc[mi][ni][j] - cs[c0 + ni * 8 + (j & 1)];
                acc[mi][ni][j] = v;
                s[mi][j >> 1] = fmaf(v, v, s[mi][j >> 1]);
            }
    #pragma unroll
    for (int mi = 0; mi < 2; mi++)
        #pragma unroll
        for (int h = 0; h < 2; h++) {
            s[mi][h] += __shfl_xor_sync(0xffffffffu, s[mi][h], 1);
            s[mi][h] += __shfl_xor_sync(0xffffffffu, s[mi][h], 2);
        }
    const int r0 = wm * 32 + (lane >> 2);
    if ((lane & 3) == 0) {
        #pragma unroll
        for (int mi = 0; mi < 2; mi++)
            #pragma unroll
            for (int h = 0; h < 2; h++)
                red[(r0 + mi * 16 + h * 8) * 4 + wn] = s[mi][h];
    }
    __syncthreads();
    // Z panel wn holds k in [wn*64, wn*64+64): 128 rows x 128B, swizzled
    #pragma unroll
    for (int mi = 0; mi < 2; mi++)
        #pragma unroll
        for (int h = 0; h < 2; h++) {
            const int r = r0 + mi * 16 + h * 8;
            float t = red[r * 4 + 0] + red[r * 4 + 1] + red[r * 4 + 2] + red[r * 4 + 3];
            float inv = 1.f / fmaxf(sqrtf(t), 1e-12f);
            const uint32_t zrow = sZ + (uint32_t)(wn * 16384 + r * 128);
            const uint32_t xr = (uint32_t)((r & 7) << 4);
            #pragma unroll
            for (int ni = 0; ni < 8; ni++) {
                __nv_bfloat162 zz = __floats2bfloat162_rn(acc[mi][ni][2 * h] * inv,
                                                          acc[mi][ni][2 * h + 1] * inv);
                const uint32_t boff = (uint32_t)((lane & 3) * 4 + ni * 16) ^ xr;
                asm volatile("st.shared.b32 [%0], %1;" :: "r"(zrow + boff),
                             "r"(*(uint32_t*)&zz) : "memory");
            }
        }

    // reuse acc for phase 2
    #pragma unroll
    for (int a = 0; a < 2; a++)
        #pragma unroll
        for (int b = 0; b < 8; b++)
            #pragma unroll
            for (int c = 0; c < 4; c++) acc[a][b][c] = 0.f;

    CP_WAIT0();        // prototype stage 0 landed
    __syncthreads();   // all Z panels visible

    // ---- phase 2: S = Z @ P^T over 4 k-stages (A = smem Z panels) ----
    for (int s2 = 0; s2 < 4; s2++) {
        const int cur = s2 & 1, nxt = cur ^ 1;
        const bool more = s2 < 3;
        if (more) {
            #pragma unroll
            for (int i = 0; i < 4; i++)
                cp16(sB + nxt * 32768 + cpBoff + i * 64 * 128,
                     gBp + (size_t)(64 * i) * D_PROJ + (s2 + 1) * KT);
            CP_COMMIT();
        }
        mma_stage(sZ + s2 * 16384, sB + cur * 32768, lane, wm, wn, acc);
        if (more) CP_WAIT0();
        __syncthreads();
    }

    // ---- final epilogue: score = -sqrt(max(1 + p2 - 2 s, 0)) ----
    #pragma unroll
    for (int mi = 0; mi < 2; mi++)
        #pragma unroll
        for (int h = 0; h < 2; h++) {
            const size_t rowoff = (size_t)(m0 + r0 + mi * 16 + h * 8) * N_CLS;
            #pragma unroll
            for (int ni = 0; ni < 8; ni++) {
                const int cc = c0 + ni * 8;
                float2 v;
                v.x = -sqrtf(fmaxf(1.0f + p2s[cc]     - 2.f * acc[mi][ni][2 * h],     0.f));
                v.y = -sqrtf(fmaxf(1.0f + p2s[cc + 1] - 2.f * acc[mi][ni][2 * h + 1], 0.f));
                *(float2*)(out + rowoff + cc) = v;
            }
        }
}

// ---------------------------------------------------------------------------
// Host launcher (graph-capturable: kernel launches only)
// ---------------------------------------------------------------------------
extern "C" void kernel_launch(void* const* d_in, const int* in_sizes, int n_in,
                              void* d_out, int out_size) {
    const float* X     = (const float*)d_in[0];
    const float* mean  = (const float*)d_in[1];
    const float* proj  = (const float*)d_in[2];
    const float* proto = (const float*)d_in[3];
    float* out = (float*)d_out;

    cudaFuncSetAttribute(proto_fused, cudaFuncAttributeMaxDynamicSharedMemorySize, SMEMF);

    proto_prep<<<80, 256>>>(mean, proj, proto);
    proto_fused<<<N_ROWS / TM, 512, SMEMF>>>(X, out);
}